// round 3
// baseline (speedup 1.0000x reference)
#include <cuda_runtime.h>
#include <cuda_bf16.h>

// PreProcesser: backbone frames + electrostatic field voxel divergence.
// Z*N=512 residues, A=14 atoms, 16^3 voxels, RES=1, X_LBL=20.
// Output: C_backbone (512*12) | divergence (512*4096) | frames (512*9).
//
// R3 (= R2 resubmit; infra timeout): fma.rn.f32x2 packed math (2 voxels/lane),
// approx rsqrt (no Newton), branchless f = r*min(r^2,1) with d2 clamp.

#define A_ 14

typedef unsigned long long ull;

__device__ __forceinline__ ull f2pack(float lo, float hi) {
    ull r; asm("mov.b64 %0, {%1, %2};" : "=l"(r) : "f"(lo), "f"(hi)); return r;
}
__device__ __forceinline__ void f2unpack(ull p, float& lo, float& hi) {
    asm("mov.b64 {%0, %1}, %2;" : "=f"(lo), "=f"(hi) : "l"(p));
}
__device__ __forceinline__ ull fadd2(ull a, ull b) {
    ull r; asm("add.rn.f32x2 %0, %1, %2;" : "=l"(r) : "l"(a), "l"(b)); return r;
}
__device__ __forceinline__ ull fmul2(ull a, ull b) {
    ull r; asm("mul.rn.f32x2 %0, %1, %2;" : "=l"(r) : "l"(a), "l"(b)); return r;
}
__device__ __forceinline__ ull ffma2(ull a, ull b, ull c) {
    ull r; asm("fma.rn.f32x2 %0, %1, %2, %3;" : "=l"(r) : "l"(a), "l"(b), "l"(c)); return r;
}
__device__ __forceinline__ float frsqrt_approx(float x) {
    float r; asm("rsqrt.approx.f32 %0, %1;" : "=f"(r) : "f"(x)); return r;
}

struct AtomP { ull nx2, ny2, nz2, q2; };   // negated coords + charge, lane-duplicated

__global__ __launch_bounds__(512, 2)
void preproc_kernel(const float* __restrict__ C,
                    const int*   __restrict__ L32,
                    const float* __restrict__ atom_mask,
                    const float* __restrict__ amber,
                    float* __restrict__ out,
                    int zn)
{
    float* out_cb  = out;                          // zn*12
    float* out_div = out + (size_t)zn * 12;        // zn*4096
    float* out_fr  = out_div + (size_t)zn * 4096;  // zn*9

    __shared__ float sS[4096];       // fx+fy+fz per voxel
    __shared__ float sTail[512];     // fx at x=14 (first 256) and x=15 (last 256)
    __shared__ AtomP sAtom[A_];
    __shared__ float sFrm[12];       // x_unit, y_unit, z_unit, origin(=cb)
    __shared__ int   sLc;

    const int res = blockIdx.x;
    const int tid = threadIdx.x;

    // ---- label load with int64/int32 dtype auto-detection (bounds-safe) ----
    if (tid == 32) {
        bool maybe64 = true;
        for (int k = 1; k < 2 * 256; k += 2) {
            int v = L32[k];
            if (v != 0 && v != -1) { maybe64 = false; break; }
        }
        long long l;
        if (maybe64) l = ((const long long*)L32)[res];
        else         l = (long long)L32[res];
        sLc = (l == -1) ? 20 : (int)l;   // X_LBL = 20
    }

    // ---- per-residue backbone + frames (thread 0) ----
    if (tid == 0) {
        const float* Cr = C + (size_t)res * (A_ * 3);
        float nx=Cr[0],  ny=Cr[1],  nz=Cr[2];
        float cax=Cr[3], cay=Cr[4], caz=Cr[5];
        float cx=Cr[6],  cy=Cr[7],  cz=Cr[8];

        float b1x=cax-nx,  b1y=cay-ny,  b1z=caz-nz;
        float b2x=cx-cax,  b2y=cy-cay,  b2z=cz-caz;
        float b3x=b1y*b2z-b1z*b2y;
        float b3y=b1z*b2x-b1x*b2z;
        float b3z=b1x*b2y-b1y*b2x;
        float cbx = cax - 0.58273431f*b2x + 0.56802827f*b1x - 0.54067466f*b3x;
        float cby = cay - 0.58273431f*b2y + 0.56802827f*b1y - 0.54067466f*b3y;
        float cbz = caz - 0.58273431f*b2z + 0.56802827f*b1z - 0.54067466f*b3z;

        float yx=cbx-cax, yy=cby-cay, yz=cbz-caz;
        float yn = sqrtf(yx*yx + yy*yy + yz*yz);
        float yd = fmaxf(yn, 1e-6f);
        float yux=yx/yd, yuy=yy/yd, yuz=yz/yd;

        // reference subtracts the SCALAR projection from every component
        float xrx=cx-nx, xry=cy-ny, xrz=cz-nz;
        float xp = xrx*yux + xry*yuy + xrz*yuz;
        float xx=xrx-xp, xy=xry-xp, xz=xrz-xp;
        float xn = sqrtf(xx*xx + xy*xy + xz*xz);
        float xd = fmaxf(xn, 1e-6f);
        float xux=xx/xd, xuy=xy/xd, xuz=xz/xd;

        float zux = xuy*yuz - xuz*yuy;
        float zuy = xuz*yux - xux*yuz;
        float zuz = xux*yuy - xuy*yux;

        float* cbp = out_cb + (size_t)res * 12;
        cbp[0]=nx;  cbp[1]=ny;  cbp[2]=nz;
        cbp[3]=cax; cbp[4]=cay; cbp[5]=caz;
        cbp[6]=cx;  cbp[7]=cy;  cbp[8]=cz;
        cbp[9]=cbx; cbp[10]=cby; cbp[11]=cbz;

        float* frp = out_fr + (size_t)res * 9;
        frp[0]=xux; frp[1]=xuy; frp[2]=xuz;
        frp[3]=yux; frp[4]=yuy; frp[5]=yuz;
        frp[6]=zux; frp[7]=zuy; frp[8]=zuz;

        sFrm[0]=xux; sFrm[1]=xuy; sFrm[2]=xuz;
        sFrm[3]=yux; sFrm[4]=yuy; sFrm[5]=yuz;
        sFrm[6]=zux; sFrm[7]=zuy; sFrm[8]=zuz;
        sFrm[9]=cbx; sFrm[10]=cby; sFrm[11]=cbz;
    }
    __syncthreads();

    if (tid < A_) {
        const float* Cr = C + (size_t)res * (A_ * 3) + tid * 3;
        float q = amber[sLc * A_ + tid] * atom_mask[(size_t)res * A_ + tid];
        float ax = Cr[0], ay = Cr[1], az = Cr[2];
        sAtom[tid].nx2 = f2pack(-ax, -ax);
        sAtom[tid].ny2 = f2pack(-ay, -ay);
        sAtom[tid].nz2 = f2pack(-az, -az);
        sAtom[tid].q2  = f2pack(q, q);
    }
    __syncthreads();

    const float xux=sFrm[0], xuy=sFrm[1], xuz=sFrm[2];
    const float yux=sFrm[3], yuy=sFrm[4], yuz=sFrm[5];
    const float zux=sFrm[6], zuy=sFrm[7], zuz=sFrm[8];
    const float ox =sFrm[9], oy =sFrm[10], oz =sFrm[11];
    // offset between paired voxels: x and x+8 -> +8*x_unit
    const float ex = 8.0f*xux, ey = 8.0f*xuy, ez = 8.0f*xuz;

    // ---- field: 4 voxel-PAIRS per thread (voxel i paired with i+2048) ----
    #pragma unroll
    for (int it = 0; it < 4; it++) {
        const int i = tid + it * 512;              // A-voxel: x in 0..7
        const float gx = (float)(i >> 8) - 8.0f;
        const float gy = (float)((i >> 4) & 15) - 4.0f;
        const float gz = (float)(i & 15) - 8.0f;

        float px = fmaf(gx, xux, fmaf(gy, yux, fmaf(gz, zux, ox)));
        float py = fmaf(gx, xuy, fmaf(gy, yuy, fmaf(gz, zuy, oy)));
        float pz = fmaf(gx, xuz, fmaf(gy, yuz, fmaf(gz, zuz, oz)));

        const ull ppx = f2pack(px, px + ex);
        const ull ppy = f2pack(py, py + ey);
        const ull ppz = f2pack(pz, pz + ez);

        ull fx2 = 0, fy2 = 0, fz2 = 0;
        #pragma unroll
        for (int a = 0; a < A_; a++) {
            const AtomP at = sAtom[a];
            ull dx2 = fadd2(ppx, at.nx2);
            ull dy2 = fadd2(ppy, at.ny2);
            ull dz2 = fadd2(ppz, at.nz2);
            ull d2p = ffma2(dz2, dz2, ffma2(dy2, dy2, fmul2(dx2, dx2)));
            float d2a, d2b; f2unpack(d2p, d2a, d2b);
            d2a = fmaxf(d2a, 1e-12f);
            d2b = fmaxf(d2b, 1e-12f);
            float ra = frsqrt_approx(d2a);
            float rb = frsqrt_approx(d2b);
            // f = r * min(r^2, 1):  d>=1 -> 1/d^3,  d<1 -> 1/d  (matches ref)
            float fa = ra * fminf(ra * ra, 1.0f);
            float fb = rb * fminf(rb * rb, 1.0f);
            ull fq2 = fmul2(f2pack(fa, fb), at.q2);
            fx2 = ffma2(dx2, fq2, fx2);
            fy2 = ffma2(dy2, fq2, fy2);
            fz2 = ffma2(dz2, fq2, fz2);
        }

        // normalize field (zero vector stays zero via clamp)
        ull fn2p = ffma2(fz2, fz2, ffma2(fy2, fy2, fmul2(fx2, fx2)));
        float n2a, n2b; f2unpack(fn2p, n2a, n2b);
        float rna = frsqrt_approx(fmaxf(n2a, 1e-30f));
        float rnb = frsqrt_approx(fmaxf(n2b, 1e-30f));
        ull rn2 = f2pack(rna, rnb);
        fx2 = fmul2(fx2, rn2);
        fy2 = fmul2(fy2, rn2);
        fz2 = fmul2(fz2, rn2);

        ull s2 = fadd2(fadd2(fx2, fy2), fz2);
        float sA, sB; f2unpack(s2, sA, sB);
        sS[i]        = sA;
        sS[i + 2048] = sB;

        const int xB = (i >> 8) + 8;
        if (xB >= 14) {
            float fxA, fxB; f2unpack(fx2, fxA, fxB);
            sTail[((xB - 14) << 8) | (i & 255)] = fxB;
        }
    }
    __syncthreads();

    // ---- divergence: all three components differenced along voxel-x,
    // with sign flips for y/z at the last plane. ----
    float* od = out_div + (size_t)res * 4096;
    #pragma unroll
    for (int it = 0; it < 8; it++) {
        int i = tid + it * 512;
        int x = i >> 8;
        float d;
        if (x == 0) {
            d = sS[i + 256] - sS[i];
        } else if (x == 15) {
            int yv = i & 255;
            // (fx15-fx14) + (fy14-fy15) + (fz14-fz15) = 2*(fx15-fx14) + S14 - S15
            d = 2.0f * (sTail[256 + yv] - sTail[yv]) + sS[i - 256] - sS[i];
        } else {
            d = 0.5f * (sS[i + 256] - sS[i - 256]);
        }
        od[i] = d;
    }
}

extern "C" void kernel_launch(void* const* d_in, const int* in_sizes, int n_in,
                              void* d_out, int out_size) {
    const float* C     = (const float*)d_in[0];   // (Z,N,14,3) f32
    const int*   L     = (const int*)d_in[1];     // (Z,N) int64-or-int32 (auto-detected)
    const float* amask = (const float*)d_in[2];   // (Z,N,14) f32
    // d_in[3] = valid_mask (unused by reference)
    const float* amber = (const float*)d_in[4];   // (21,14) f32
    int zn = in_sizes[1];                         // Z*N = 512
    preproc_kernel<<<zn, 512>>>(C, L, amask, amber, (float*)d_out, zn);
}

// round 8
// speedup vs baseline: 1.8133x; 1.8133x over previous
#include <cuda_runtime.h>
#include <cuda_bf16.h>

// PreProcesser: backbone frames + electrostatic field voxel divergence.
// Z*N=512 residues, A=14 atoms, 16^3 voxels, RES=1, X_LBL=20.
// Output: C_backbone (512*12) | divergence (512*4096) | frames (512*9).
//
// R8 (= R4 resubmit; repeated infra timeouts): scalar structure + approx
// rsqrt (no Newton) + branchless f = r*min(r^2,1) + warp-parallel label
// dtype detection.

#define A_ 14

__device__ __forceinline__ float frsqrt_approx(float x) {
    float r; asm("rsqrt.approx.f32 %0, %1;" : "=f"(r) : "f"(x)); return r;
}

__global__ __launch_bounds__(512, 2)
void preproc_kernel(const float* __restrict__ C,
                    const int*   __restrict__ L32,
                    const float* __restrict__ atom_mask,
                    const float* __restrict__ amber,
                    float* __restrict__ out,
                    int zn)
{
    float* out_cb  = out;                          // zn*12
    float* out_div = out + (size_t)zn * 12;        // zn*4096
    float* out_fr  = out_div + (size_t)zn * 4096;  // zn*9

    __shared__ float  sS[4096];      // fx+fy+fz per voxel
    __shared__ float  sTail[512];    // fx at x=14 (first 256) and x=15 (last 256)
    __shared__ float4 sAtom[A_];     // (ax, ay, az, charge)
    __shared__ float  sFrm[12];      // x_unit, y_unit, z_unit, origin(=cb)
    __shared__ int    sLc;

    const int res = blockIdx.x;
    const int tid = threadIdx.x;

    // ---- label dtype detection, parallel across warp 1 (tids 32..63) ----
    // If L is int64 (little endian), every odd 32-bit word is the high word of
    // a value in [-1, 21) -> must be 0 or -1. 32 lanes x 8 odd words = 256.
    if (tid >= 32 && tid < 64) {
        int lane = tid - 32;
        bool ok = true;
        #pragma unroll
        for (int j = 0; j < 8; j++) {
            int v = L32[1 + 2 * (lane * 8 + j)];   // reads <= index 511: safe either way
            ok &= (v == 0) | (v == -1);
        }
        bool all64 = __all_sync(0xffffffffu, ok);
        if (lane == 0) {
            long long l = all64 ? ((const long long*)L32)[res]
                                : (long long)L32[res];
            sLc = (l == -1) ? 20 : (int)l;         // X_LBL = 20
        }
    }

    // ---- per-residue backbone + frames (thread 0) ----
    if (tid == 0) {
        const float* Cr = C + (size_t)res * (A_ * 3);
        float nx=Cr[0],  ny=Cr[1],  nz=Cr[2];
        float cax=Cr[3], cay=Cr[4], caz=Cr[5];
        float cx=Cr[6],  cy=Cr[7],  cz=Cr[8];

        float b1x=cax-nx,  b1y=cay-ny,  b1z=caz-nz;
        float b2x=cx-cax,  b2y=cy-cay,  b2z=cz-caz;
        float b3x=b1y*b2z-b1z*b2y;
        float b3y=b1z*b2x-b1x*b2z;
        float b3z=b1x*b2y-b1y*b2x;
        float cbx = cax - 0.58273431f*b2x + 0.56802827f*b1x - 0.54067466f*b3x;
        float cby = cay - 0.58273431f*b2y + 0.56802827f*b1y - 0.54067466f*b3y;
        float cbz = caz - 0.58273431f*b2z + 0.56802827f*b1z - 0.54067466f*b3z;

        // y = cb - ca   (full precision here: tiny cost, feeds everything)
        float yx=cbx-cax, yy=cby-cay, yz=cbz-caz;
        float yn = sqrtf(yx*yx + yy*yy + yz*yz);
        float yd = fmaxf(yn, 1e-6f);
        float yux=yx/yd, yuy=yy/yd, yuz=yz/yd;

        // x_raw = c - n; reference subtracts the SCALAR projection from every
        // component (bug-compatible).
        float xrx=cx-nx, xry=cy-ny, xrz=cz-nz;
        float xp = xrx*yux + xry*yuy + xrz*yuz;
        float xx=xrx-xp, xy=xry-xp, xz=xrz-xp;
        float xn = sqrtf(xx*xx + xy*xy + xz*xz);
        float xd = fmaxf(xn, 1e-6f);
        float xux=xx/xd, xuy=xy/xd, xuz=xz/xd;

        float zux = xuy*yuz - xuz*yuy;
        float zuy = xuz*yux - xux*yuz;
        float zuz = xux*yuy - xuy*yux;

        float* cbp = out_cb + (size_t)res * 12;
        cbp[0]=nx;  cbp[1]=ny;  cbp[2]=nz;
        cbp[3]=cax; cbp[4]=cay; cbp[5]=caz;
        cbp[6]=cx;  cbp[7]=cy;  cbp[8]=cz;
        cbp[9]=cbx; cbp[10]=cby; cbp[11]=cbz;

        float* frp = out_fr + (size_t)res * 9;
        frp[0]=xux; frp[1]=xuy; frp[2]=xuz;
        frp[3]=yux; frp[4]=yuy; frp[5]=yuz;
        frp[6]=zux; frp[7]=zuy; frp[8]=zuz;

        sFrm[0]=xux; sFrm[1]=xuy; sFrm[2]=xuz;
        sFrm[3]=yux; sFrm[4]=yuy; sFrm[5]=yuz;
        sFrm[6]=zux; sFrm[7]=zuy; sFrm[8]=zuz;
        sFrm[9]=cbx; sFrm[10]=cby; sFrm[11]=cbz;   // origin = cb
    }
    __syncthreads();

    if (tid < A_) {
        const float* Cr = C + (size_t)res * (A_ * 3) + tid * 3;
        float q = amber[sLc * A_ + tid] * atom_mask[(size_t)res * A_ + tid];
        sAtom[tid] = make_float4(Cr[0], Cr[1], Cr[2], q);
    }
    __syncthreads();

    const float xux=sFrm[0], xuy=sFrm[1], xuz=sFrm[2];
    const float yux=sFrm[3], yuy=sFrm[4], yuz=sFrm[5];
    const float zux=sFrm[6], zuy=sFrm[7], zuz=sFrm[8];
    const float ox =sFrm[9], oy =sFrm[10], oz =sFrm[11];

    // ---- field per voxel: 8 voxels/thread ----
    #pragma unroll
    for (int it = 0; it < 8; it++) {
        int i = tid + it * 512;
        float gx = (float)(i >> 8) - 8.0f;
        float gy = (float)((i >> 4) & 15) - 4.0f;
        float gz = (float)(i & 15) - 8.0f;
        float px = fmaf(gx, xux, fmaf(gy, yux, fmaf(gz, zux, ox)));
        float py = fmaf(gx, xuy, fmaf(gy, yuy, fmaf(gz, zuy, oy)));
        float pz = fmaf(gx, xuz, fmaf(gy, yuz, fmaf(gz, zuz, oz)));

        float fx=0.f, fy=0.f, fz=0.f;
        #pragma unroll
        for (int a = 0; a < A_; a++) {
            float4 at = sAtom[a];
            float dx = px - at.x, dy = py - at.y, dz = pz - at.z;
            float d2 = fmaf(dz, dz, fmaf(dy, dy, dx * dx));
            d2 = fmaxf(d2, 1e-12f);
            float r = frsqrt_approx(d2);
            // factor: d>=1 -> 1/d^3, d<1 -> 1/d  ==  r * min(r^2, 1)
            // at d==0 (clamped): dx=dy=dz=0 so contribution is exactly 0.
            float f = (r * at.w) * fminf(r * r, 1.0f);
            fx = fmaf(dx, f, fx);
            fy = fmaf(dy, f, fy);
            fz = fmaf(dz, f, fz);
        }

        // normalize field (zero vector stays zero: numerators are 0)
        float fn2 = fmaf(fx, fx, fmaf(fy, fy, fz * fz));
        float rn = frsqrt_approx(fmaxf(fn2, 1e-30f));
        fx *= rn; fy *= rn; fz *= rn;

        sS[i] = fx + fy + fz;
        int x = i >> 8;
        if (x >= 14) sTail[((x - 14) << 8) | (i & 255)] = fx;
    }
    __syncthreads();

    // ---- divergence: all three components differenced along voxel-x,
    // with sign flips for y/z at the last plane. ----
    float* od = out_div + (size_t)res * 4096;
    #pragma unroll
    for (int it = 0; it < 8; it++) {
        int i = tid + it * 512;
        int x = i >> 8;
        float d;
        if (x == 0) {
            d = sS[i + 256] - sS[i];
        } else if (x == 15) {
            int yv = i & 255;
            // (fx15-fx14) + (fy14-fy15) + (fz14-fz15) = 2*(fx15-fx14) + S14 - S15
            d = 2.0f * (sTail[256 + yv] - sTail[yv]) + sS[i - 256] - sS[i];
        } else {
            d = 0.5f * (sS[i + 256] - sS[i - 256]);
        }
        od[i] = d;
    }
}

extern "C" void kernel_launch(void* const* d_in, const int* in_sizes, int n_in,
                              void* d_out, int out_size) {
    const float* C     = (const float*)d_in[0];   // (Z,N,14,3) f32
    const int*   L     = (const int*)d_in[1];     // (Z,N) int64-or-int32 (auto-detected)
    const float* amask = (const float*)d_in[2];   // (Z,N,14) f32
    // d_in[3] = valid_mask (unused by reference)
    const float* amber = (const float*)d_in[4];   // (21,14) f32
    int zn = in_sizes[1];                         // Z*N = 512
    preproc_kernel<<<zn, 512>>>(C, L, amask, amber, (float*)d_out, zn);
}

// round 9
// speedup vs baseline: 1.9621x; 1.0821x over previous
#include <cuda_runtime.h>
#include <cuda_bf16.h>

// PreProcesser: backbone frames + electrostatic field voxel divergence.
// Z*N=512 residues, A=14 atoms, 16^3 voxels, RES=1, X_LBL=20.
// Output: C_backbone (512*12) | divergence (512*4096) | frames (512*9).
//
// R9: split each residue across 2 blocks of 256 threads (y-halves) to fix
// wave quantization (512 blocks/296 slots -> makespan 2.0 units; 1024
// half-blocks -> ~1.75). Keeps R8 math: approx rsqrt, branchless factor.

#define A_ 14

__device__ __forceinline__ float frsqrt_approx(float x) {
    float r; asm("rsqrt.approx.f32 %0, %1;" : "=f"(r) : "f"(x)); return r;
}

__global__ __launch_bounds__(256, 4)
void preproc_kernel(const float* __restrict__ C,
                    const int*   __restrict__ L32,
                    const float* __restrict__ atom_mask,
                    const float* __restrict__ amber,
                    float* __restrict__ out,
                    int zn)
{
    float* out_cb  = out;                          // zn*12
    float* out_div = out + (size_t)zn * 12;        // zn*4096
    float* out_fr  = out_div + (size_t)zn * 4096;  // zn*9

    __shared__ float  sS[2048];      // fx+fy+fz, this block's half: [x][yy][v]
    __shared__ float  sTail[256];    // fx at x=14 (first 128) and x=15 (last 128)
    __shared__ float4 sAtom[A_];     // (ax, ay, az, charge)
    __shared__ float  sFrm[12];      // x_unit, y_unit, z_unit, origin(=cb)
    __shared__ int    sLc;

    const int res  = blockIdx.x >> 1;
    const int half = blockIdx.x & 1;       // y in [half*8, half*8+8)
    const int y0   = half << 3;
    const int tid  = threadIdx.x;

    // ---- label dtype detection, parallel across warp 1 (tids 32..63) ----
    // If L is int64 (little endian), every odd 32-bit word is the high word of
    // a value in [-1, 21) -> must be 0 or -1. 32 lanes x 8 odd words = 256.
    if (tid >= 32 && tid < 64) {
        int lane = tid - 32;
        bool ok = true;
        #pragma unroll
        for (int j = 0; j < 8; j++) {
            int v = L32[1 + 2 * (lane * 8 + j)];   // reads <= index 511: safe either way
            ok &= (v == 0) | (v == -1);
        }
        bool all64 = __all_sync(0xffffffffu, ok);
        if (lane == 0) {
            long long l = all64 ? ((const long long*)L32)[res]
                                : (long long)L32[res];
            sLc = (l == -1) ? 20 : (int)l;         // X_LBL = 20
        }
    }

    // ---- per-residue backbone + frames (thread 0; gmem writes from half 0) ----
    if (tid == 0) {
        const float* Cr = C + (size_t)res * (A_ * 3);
        float nx=Cr[0],  ny=Cr[1],  nz=Cr[2];
        float cax=Cr[3], cay=Cr[4], caz=Cr[5];
        float cx=Cr[6],  cy=Cr[7],  cz=Cr[8];

        float b1x=cax-nx,  b1y=cay-ny,  b1z=caz-nz;
        float b2x=cx-cax,  b2y=cy-cay,  b2z=cz-caz;
        float b3x=b1y*b2z-b1z*b2y;
        float b3y=b1z*b2x-b1x*b2z;
        float b3z=b1x*b2y-b1y*b2x;
        float cbx = cax - 0.58273431f*b2x + 0.56802827f*b1x - 0.54067466f*b3x;
        float cby = cay - 0.58273431f*b2y + 0.56802827f*b1y - 0.54067466f*b3y;
        float cbz = caz - 0.58273431f*b2z + 0.56802827f*b1z - 0.54067466f*b3z;

        // y = cb - ca
        float yx=cbx-cax, yy=cby-cay, yz=cbz-caz;
        float yn = sqrtf(yx*yx + yy*yy + yz*yz);
        float yd = fmaxf(yn, 1e-6f);
        float yux=yx/yd, yuy=yy/yd, yuz=yz/yd;

        // x_raw = c - n; reference subtracts the SCALAR projection from every
        // component (bug-compatible).
        float xrx=cx-nx, xry=cy-ny, xrz=cz-nz;
        float xp = xrx*yux + xry*yuy + xrz*yuz;
        float xx=xrx-xp, xy=xry-xp, xz=xrz-xp;
        float xn = sqrtf(xx*xx + xy*xy + xz*xz);
        float xd = fmaxf(xn, 1e-6f);
        float xux=xx/xd, xuy=xy/xd, xuz=xz/xd;

        float zux = xuy*yuz - xuz*yuy;
        float zuy = xuz*yux - xux*yuz;
        float zuz = xux*yuy - xuy*yux;

        if (half == 0) {
            float* cbp = out_cb + (size_t)res * 12;
            cbp[0]=nx;  cbp[1]=ny;  cbp[2]=nz;
            cbp[3]=cax; cbp[4]=cay; cbp[5]=caz;
            cbp[6]=cx;  cbp[7]=cy;  cbp[8]=cz;
            cbp[9]=cbx; cbp[10]=cby; cbp[11]=cbz;

            float* frp = out_fr + (size_t)res * 9;
            frp[0]=xux; frp[1]=xuy; frp[2]=xuz;
            frp[3]=yux; frp[4]=yuy; frp[5]=yuz;
            frp[6]=zux; frp[7]=zuy; frp[8]=zuz;
        }

        sFrm[0]=xux; sFrm[1]=xuy; sFrm[2]=xuz;
        sFrm[3]=yux; sFrm[4]=yuy; sFrm[5]=yuz;
        sFrm[6]=zux; sFrm[7]=zuy; sFrm[8]=zuz;
        sFrm[9]=cbx; sFrm[10]=cby; sFrm[11]=cbz;   // origin = cb
    }
    __syncthreads();

    if (tid < A_) {
        const float* Cr = C + (size_t)res * (A_ * 3) + tid * 3;
        float q = amber[sLc * A_ + tid] * atom_mask[(size_t)res * A_ + tid];
        sAtom[tid] = make_float4(Cr[0], Cr[1], Cr[2], q);
    }
    __syncthreads();

    const float xux=sFrm[0], xuy=sFrm[1], xuz=sFrm[2];
    const float yux=sFrm[3], yuy=sFrm[4], yuz=sFrm[5];
    const float zux=sFrm[6], zuy=sFrm[7], zuz=sFrm[8];
    const float ox =sFrm[9], oy =sFrm[10], oz =sFrm[11];

    // ---- field per voxel: 8 voxels/thread over this y-half ----
    // local index j = x*128 + yy*16 + v   (x:0..15, yy:0..7, v:0..15)
    #pragma unroll
    for (int it = 0; it < 8; it++) {
        int j = tid + it * 256;
        float gx = (float)(j >> 7) - 8.0f;
        float gy = (float)(y0 + ((j >> 4) & 7)) - 4.0f;
        float gz = (float)(j & 15) - 8.0f;
        float px = fmaf(gx, xux, fmaf(gy, yux, fmaf(gz, zux, ox)));
        float py = fmaf(gx, xuy, fmaf(gy, yuy, fmaf(gz, zuy, oy)));
        float pz = fmaf(gx, xuz, fmaf(gy, yuz, fmaf(gz, zuz, oz)));

        float fx=0.f, fy=0.f, fz=0.f;
        #pragma unroll
        for (int a = 0; a < A_; a++) {
            float4 at = sAtom[a];
            float dx = px - at.x, dy = py - at.y, dz = pz - at.z;
            float d2 = fmaf(dz, dz, fmaf(dy, dy, dx * dx));
            d2 = fmaxf(d2, 1e-12f);
            float r = frsqrt_approx(d2);
            // factor: d>=1 -> 1/d^3, d<1 -> 1/d  ==  r * min(r^2, 1)
            // at d==0 (clamped): dx=dy=dz=0 so contribution is exactly 0.
            float f = (r * at.w) * fminf(r * r, 1.0f);
            fx = fmaf(dx, f, fx);
            fy = fmaf(dy, f, fy);
            fz = fmaf(dz, f, fz);
        }

        // normalize field (zero vector stays zero: numerators are 0)
        float fn2 = fmaf(fx, fx, fmaf(fy, fy, fz * fz));
        float rn = frsqrt_approx(fmaxf(fn2, 1e-30f));
        fx *= rn; fy *= rn; fz *= rn;

        sS[j] = fx + fy + fz;
        int x = j >> 7;
        if (x >= 14) sTail[((x - 14) << 7) | (j & 127)] = fx;
    }
    __syncthreads();

    // ---- divergence: all three components differenced along voxel-x,
    // with sign flips for y/z at the last plane. ----
    float* od = out_div + (size_t)res * 4096 + (y0 << 4);
    #pragma unroll
    for (int it = 0; it < 8; it++) {
        int j = tid + it * 256;
        int x = j >> 7;
        float d;
        if (x == 0) {
            d = sS[j + 128] - sS[j];
        } else if (x == 15) {
            int yv = j & 127;
            // (fx15-fx14) + (fy14-fy15) + (fz14-fz15) = 2*(fx15-fx14) + S14 - S15
            d = 2.0f * (sTail[128 + yv] - sTail[yv]) + sS[j - 128] - sS[j];
        } else {
            d = 0.5f * (sS[j + 128] - sS[j - 128]);
        }
        // global voxel index: x*256 + (y0+yy)*16 + v
        od[((j & ~127) << 1) + (j & 127)] = d;
    }
}

extern "C" void kernel_launch(void* const* d_in, const int* in_sizes, int n_in,
                              void* d_out, int out_size) {
    const float* C     = (const float*)d_in[0];   // (Z,N,14,3) f32
    const int*   L     = (const int*)d_in[1];     // (Z,N) int64-or-int32 (auto-detected)
    const float* amask = (const float*)d_in[2];   // (Z,N,14) f32
    // d_in[3] = valid_mask (unused by reference)
    const float* amber = (const float*)d_in[4];   // (21,14) f32
    int zn = in_sizes[1];                         // Z*N = 512
    preproc_kernel<<<zn * 2, 256>>>(C, L, amask, amber, (float*)d_out, zn);
}